// round 14
// baseline (speedup 1.0000x reference)
#include <cuda_runtime.h>
#include <cuda_fp16.h>
#include <math.h>
#include <stdint.h>

// ---------------- problem dims ----------------------------------------------
#define B_DIM 4
#define S_DIM 4096
#define D_IN  1024
#define N_ST  1024
#define M_DIM (B_DIM * S_DIM)      // 16384
#define K_DIM 1024

typedef unsigned long long ull;

// ---------------- static scratch ---------------------------------------------
__device__ __half g_prj [(size_t)M_DIM * 3072];      // [xp | r | i] fp16
__device__ ull    g_x16 [(size_t)M_DIM * K_DIM / 4]; // fp16 x
__device__ ull    g_hs16[(size_t)M_DIM * N_ST / 4];  // fp16 hs
__device__ ull    g_w16 [4 * 1024 * 1024 / 4];       // fp16 W_in,W_r,W_i,W_out
__device__ float  g_b3  [3072];                      // concat(b_in, b_r, b_i)

// ---------------- asm helpers -------------------------------------------------
__device__ __forceinline__ uint32_t s2u(const void* p) {
    uint32_t a;
    asm("{ .reg .u64 t; cvta.to.shared.u64 t, %1; cvt.u32.u64 %0, t; }"
        : "=r"(a) : "l"(p));
    return a;
}
__device__ __forceinline__ void ldsm4(uint32_t* r, uint32_t a) {
    asm volatile("ldmatrix.sync.aligned.m8n8.x4.shared.b16 {%0,%1,%2,%3},[%4];"
                 : "=r"(r[0]), "=r"(r[1]), "=r"(r[2]), "=r"(r[3]) : "r"(a));
}
__device__ __forceinline__ void mma_f16(float* d, const uint32_t* a,
                                        uint32_t b0, uint32_t b1) {
    asm volatile("mma.sync.aligned.m16n8k16.row.col.f32.f16.f16.f32 "
                 "{%0,%1,%2,%3},{%4,%5,%6,%7},{%8,%9},{%0,%1,%2,%3};"
                 : "+f"(d[0]), "+f"(d[1]), "+f"(d[2]), "+f"(d[3])
                 : "r"(a[0]), "r"(a[1]), "r"(a[2]), "r"(a[3]), "r"(b0), "r"(b1));
}
__device__ __forceinline__ void cpasync16(uint32_t s, const void* g) {
    asm volatile("cp.async.cg.shared.global [%0],[%1],16;" :: "r"(s), "l"(g));
}
__device__ __forceinline__ float sqrt_approx(float x) {
    float y;
    asm("sqrt.approx.f32 %0, %1;" : "=f"(y) : "f"(x));
    return y;
}

// ---------------- fused fp16 conversion (x + 4 weights, one launch) ----------
__device__ __forceinline__ ull pack_f16(float4 v) {
    const float* f = &v.x;
    ull p = 0;
#pragma unroll
    for (int j = 0; j < 4; j++)
        p |= (ull)__half_as_ushort(__float2half_rn(f[j])) << (16 * j);
    return p;
}
// x: 4194304 float4s -> dx; weights: 4 x 262144 float4s -> dw (contiguous)
__global__ void conv_all(const float4* __restrict__ x,
                         const float4* __restrict__ w0, const float4* __restrict__ w1,
                         const float4* __restrict__ w2, const float4* __restrict__ w3,
                         ull* __restrict__ dx, ull* __restrict__ dw)
{
    const int gid = blockIdx.x * blockDim.x + threadIdx.x;
    const int NX = M_DIM * K_DIM / 4;          // 4194304
    if (gid < NX) {
        dx[gid] = pack_f16(x[gid]);
    } else {
        const int j = gid - NX;                // 0 .. 4*262144-1
        const int seg = j >> 18, off = j & 0x3FFFF;
        const float4* src = (seg == 0) ? w0 : (seg == 1) ? w1 : (seg == 2) ? w2 : w3;
        dw[j] = pack_f16(src[off]);
    }
}
__global__ void concat_bias3(const float* __restrict__ a, const float* __restrict__ b,
                             const float* __restrict__ c, float* __restrict__ dst) {
    int t = blockIdx.x * blockDim.x + threadIdx.x;   // 3 x 1024
    dst[t] = (t < 1024) ? a[t] : (t < 2048 ? b[t - 1024] : c[t - 2048]);
}

// ---------------- fp16 MMA GEMM ------------------------------------------------
// C[m,n] = sum_k A[m,k]*B[n,k] + bias[n]; A: MxK, B: NxK, K-contiguous.
// OUT16=1 -> fp16 output, OUT16=0 -> fp32 output.
constexpr int BM = 128, BN = 128, BK = 64, STAGES = 3;
constexpr int AB_BYTES = BM * BK * 2;          // 16384 per operand tile
constexpr int STAGE_BYTES = 2 * AB_BYTES;      // 32768 (A, B)
constexpr int GSMEM = STAGES * STAGE_BYTES;    // 98304 -> 2 CTAs/SM
constexpr int NT = K_DIM / BK;                 // 16

template<int OUT16>
__global__ void __launch_bounds__(256, 2)
gemm_f16(const __half* __restrict__ A, const __half* __restrict__ B,
         const float* __restrict__ bias, void* __restrict__ Cv, int ldc)
{
    extern __shared__ char smem[];
    const uint32_t sb = s2u(smem);
    const int tid = threadIdx.x, lane = tid & 31, wid = tid >> 5;
    const int wm = wid >> 2, wn = wid & 3;          // 2 x 4 warp grid
    const int mBase = blockIdx.y * BM, nBase = blockIdx.x * BN;

    const int lrow = tid >> 1;                 // 0..127
    const int lc0  = (tid & 1) * 4;            // 16B-chunk base: 0 or 4
    const char* gA = (const char*)(A + (size_t)(mBase + lrow) * K_DIM);
    const char* gB = (const char*)(B + (size_t)(nBase + lrow) * K_DIM);
    const uint32_t swBase = lrow * 128;

    auto issue = [&](int kt, int s) {
        const uint32_t st = sb + s * STAGE_BYTES;
#pragma unroll
        for (int m = 0; m < 2; m++) {
            const char* g = (m == 0 ? gA : gB) + kt * 128;
            const uint32_t t0 = st + m * AB_BYTES + swBase;
#pragma unroll
            for (int c = 0; c < 4; c++) {
                const int cc = lc0 + c;
                cpasync16(t0 + ((cc ^ (lrow & 7)) << 4), g + cc * 16);
            }
        }
        asm volatile("cp.async.commit_group;");
    };

    float acc[4][4][4];
#pragma unroll
    for (int a = 0; a < 4; a++)
#pragma unroll
        for (int b = 0; b < 4; b++)
#pragma unroll
            for (int c = 0; c < 4; c++) acc[a][b][c] = 0.0f;

    issue(0, 0);
    issue(1, 1);

    const int li = lane >> 3, lj = lane & 7;

    for (int kt = 0; kt < NT; kt++) {
        asm volatile("cp.async.wait_group %0;" :: "n"(1));
        __syncthreads();   // single barrier: joins waits AND fences prev consumption
        if (kt + 2 < NT) issue(kt + 2, (kt + 2) % STAGES);
        else asm volatile("cp.async.commit_group;");

        const uint32_t st = sb + (kt % STAGES) * STAGE_BYTES;
        const uint32_t aS = st, bS = st + AB_BYTES;

#pragma unroll
        for (int ks = 0; ks < BK / 16; ks++) {
            uint32_t ar[4][4], br[2][4];
#pragma unroll
            for (int mt = 0; mt < 4; mt++) {
                const int r  = wm * 64 + mt * 16 + ((li & 1) << 3) + lj;
                const int c8 = ks * 2 + (li >> 1);
                ldsm4(ar[mt], aS + r * 128 + ((c8 ^ (r & 7)) << 4));
            }
#pragma unroll
            for (int n2 = 0; n2 < 2; n2++) {
                const int r  = wn * 32 + n2 * 16 + ((li >> 1) << 3) + lj;
                const int c8 = ks * 2 + (li & 1);
                ldsm4(br[n2], bS + r * 128 + ((c8 ^ (r & 7)) << 4));
            }
#pragma unroll
            for (int mt = 0; mt < 4; mt++)
#pragma unroll
                for (int nt = 0; nt < 4; nt++) {
                    const int n2 = nt >> 1, hh = (nt & 1) * 2;
                    mma_f16(acc[mt][nt], ar[mt], br[n2][hh], br[n2][hh + 1]);
                }
        }
    }

    const int grp = lane >> 2, tq = lane & 3;
#pragma unroll
    for (int nt = 0; nt < 4; nt++) {
        const int col = nBase + wn * 32 + nt * 8 + tq * 2;
        const float2 bv = *(const float2*)&bias[col];
#pragma unroll
        for (int mt = 0; mt < 4; mt++) {
            const int r0 = mBase + wm * 64 + mt * 16 + grp;
            if (OUT16) {
                __half* C = (__half*)Cv;
                __half2 v0 = __floats2half2_rn(acc[mt][nt][0] + bv.x,
                                               acc[mt][nt][1] + bv.y);
                __half2 v1 = __floats2half2_rn(acc[mt][nt][2] + bv.x,
                                               acc[mt][nt][3] + bv.y);
                *(__half2*)&C[(size_t)r0 * ldc + col]       = v0;
                *(__half2*)&C[(size_t)(r0 + 8) * ldc + col] = v1;
            } else {
                float* C = (float*)Cv;
                float2 v0 = make_float2(acc[mt][nt][0] + bv.x, acc[mt][nt][1] + bv.y);
                float2 v1 = make_float2(acc[mt][nt][2] + bv.x, acc[mt][nt][3] + bv.y);
                *(float2*)&C[(size_t)r0 * ldc + col]       = v0;
                *(float2*)&C[(size_t)(r0 + 8) * ldc + col] = v1;
            }
        }
    }
}

// ---------------- chunked gate + scan -----------------------------------------
// a = sigmoid(-8*softplus(ld)*r) < 0.5 strictly, so a 32-step warmup
// reconstructs the state to < 2^-32: chunks are fully independent.
// SC_CH=64 doubles the grid (2048 blocks -> ~86% occupancy; scan is
// latency-bound so parallelism, not traffic, is the binding resource).
constexpr int SC_CH = 64, SC_LEN = 64, SC_WARM = 32;

__device__ __forceinline__ float sigm(float x) { return 1.0f / (1.0f + __expf(-x)); }

__global__ void scan_kernel(const float* __restrict__ h0,
                            const float* __restrict__ ldec,
                            __half* __restrict__ hs16,
                            float* __restrict__ hlast)
{
    const int n  = blockIdx.x * 128 + threadIdx.x;   // grid.x = 8
    const int b  = blockIdx.y;                       // 4
    const int ch = blockIdx.z;                       // 64
    const float ld = ldec[n];
    const float sp = (ld > 20.0f) ? ld : log1pf(__expf(ld));
    const float c  = -8.0f * sp;
    const size_t baseP = ((size_t)b * S_DIM) * 3072 + n;    // g_prj rows (fp16)
    const size_t baseH = ((size_t)b * S_DIM) * N_ST + n;    // hs rows

    float h; int s;
    if (ch == 0) { h = h0[b * N_ST + n]; s = 0; }
    else         { h = 0.0f; s = ch * SC_LEN - SC_WARM; }
    const int s1 = ch * SC_LEN, s2 = s1 + SC_LEN;

#pragma unroll 8
    for (; s < s1; ++s) {
        const size_t ip = baseP + (size_t)s * 3072;
        const float xv = __half2float(g_prj[ip]);
        const float rv = sigm(__half2float(g_prj[ip + 1024]));
        const float iv = sigm(__half2float(g_prj[ip + 2048]));
        const float a  = sigm(c * rv);
        const float u  = sqrt_approx(fmaf(-a, a, 1.000001f)) * iv * xv;
        h = fmaf(a, h, u);
    }
#pragma unroll 4
    for (; s < s2; ++s) {
        const size_t ip = baseP + (size_t)s * 3072;
        const float xv = __half2float(g_prj[ip]);
        const float rv = sigm(__half2float(g_prj[ip + 1024]));
        const float iv = sigm(__half2float(g_prj[ip + 2048]));
        const float a  = sigm(c * rv);
        const float u  = sqrt_approx(fmaf(-a, a, 1.000001f)) * iv * xv;
        h = fmaf(a, h, u);
        hs16[baseH + (size_t)s * N_ST] = __float2half_rn(h);
    }
    if (ch == SC_CH - 1 && hlast) hlast[b * N_ST + n] = h;
}

// ---------------- host launcher -----------------------------------------------
extern "C" void kernel_launch(void* const* d_in, const int* in_sizes, int n_in,
                              void* d_out, int out_size)
{
    const float* x         = (const float*)d_in[0];
    const float* h0        = (const float*)d_in[1];
    const float* W_in      = (const float*)d_in[2];
    const float* b_in      = (const float*)d_in[3];
    const float* W_r       = (const float*)d_in[4];
    const float* b_r       = (const float*)d_in[5];
    const float* W_i       = (const float*)d_in[6];
    const float* b_i       = (const float*)d_in[7];
    const float* log_decay = (const float*)d_in[8];
    const float* W_out     = (const float*)d_in[9];
    const float* b_out     = (const float*)d_in[10];
    float* out = (float*)d_out;

    void *p_prj, *p_x16, *p_hs16, *p_w16, *p_b3;
    cudaGetSymbolAddress(&p_prj,  g_prj);
    cudaGetSymbolAddress(&p_x16,  g_x16);
    cudaGetSymbolAddress(&p_hs16, g_hs16);
    cudaGetSymbolAddress(&p_w16,  g_w16);
    cudaGetSymbolAddress(&p_b3,   g_b3);

    cudaFuncSetAttribute(gemm_f16<1>, cudaFuncAttributeMaxDynamicSharedMemorySize, GSMEM);
    cudaFuncSetAttribute(gemm_f16<0>, cudaFuncAttributeMaxDynamicSharedMemorySize, GSMEM);

    const size_t WSZ = 1024 * 1024;   // elements per weight matrix
    ull* w16 = (ull*)p_w16;

    // 1) single fused fp16 conversion (x + W_in + W_r + W_i + W_out)
    const int TOT4 = M_DIM * K_DIM / 4 + 4 * (int)(WSZ / 4);   // 5242880
    conv_all<<<TOT4 / 256, 256>>>(
        (const float4*)x, (const float4*)W_in, (const float4*)W_r,
        (const float4*)W_i, (const float4*)W_out, (ull*)p_x16, w16);
    concat_bias3<<<3, 1024>>>(b_in, b_r, b_i, (float*)p_b3);

    // 2) fused projections: [xp | r | i] = x @ [W_in;W_r;W_i]^T  (N = 3072, fp16 out)
    gemm_f16<1><<<dim3(24, 128), 256, GSMEM>>>(
        (const __half*)p_x16, (const __half*)p_w16,
        (const float*)p_b3, p_prj, 3072);

    // 3) gated scan (independent chunks via 32-step warmup)
    const long long need = (long long)M_DIM * D_IN + (long long)B_DIM * N_ST;
    float* hlast = ((long long)out_size >= need) ? out + (size_t)M_DIM * D_IN : nullptr;
    scan_kernel<<<dim3(8, 4, SC_CH), 128>>>(h0, log_decay, (__half*)p_hs16, hlast);

    // 4) output projection (N = 1024, fp32 out)
    gemm_f16<0><<<dim3(8, 128), 256, GSMEM>>>(
        (const __half*)p_hs16, (const __half*)(w16 + 3 * WSZ / 4),
        b_out, out, 1024);
}

// round 15
// speedup vs baseline: 1.0980x; 1.0980x over previous
#include <cuda_runtime.h>
#include <cuda_fp16.h>
#include <math.h>
#include <stdint.h>

// ---------------- problem dims ----------------------------------------------
#define B_DIM 4
#define S_DIM 4096
#define D_IN  1024
#define N_ST  1024
#define M_DIM (B_DIM * S_DIM)      // 16384
#define K_DIM 1024

typedef unsigned long long ull;

// ---------------- static scratch ---------------------------------------------
__device__ __half g_prj [(size_t)M_DIM * 3072];      // [xp | r | i] fp16
__device__ ull    g_au  [(size_t)M_DIM * N_ST / 2];  // packed (a,u) half2 per eln
__device__ ull    g_x16 [(size_t)M_DIM * K_DIM / 4]; // fp16 x
__device__ ull    g_hs16[(size_t)M_DIM * N_ST / 4];  // fp16 hs
__device__ ull    g_w16 [4 * 1024 * 1024 / 4];       // fp16 W_in,W_r,W_i,W_out
__device__ float  g_b3  [3072];                      // concat(b_in, b_r, b_i)
__device__ float  g_c   [1024];                      // -8 * softplus(log_decay)

// ---------------- asm helpers -------------------------------------------------
__device__ __forceinline__ uint32_t s2u(const void* p) {
    uint32_t a;
    asm("{ .reg .u64 t; cvta.to.shared.u64 t, %1; cvt.u32.u64 %0, t; }"
        : "=r"(a) : "l"(p));
    return a;
}
__device__ __forceinline__ void ldsm4(uint32_t* r, uint32_t a) {
    asm volatile("ldmatrix.sync.aligned.m8n8.x4.shared.b16 {%0,%1,%2,%3},[%4];"
                 : "=r"(r[0]), "=r"(r[1]), "=r"(r[2]), "=r"(r[3]) : "r"(a));
}
__device__ __forceinline__ void mma_f16(float* d, const uint32_t* a,
                                        uint32_t b0, uint32_t b1) {
    asm volatile("mma.sync.aligned.m16n8k16.row.col.f32.f16.f16.f32 "
                 "{%0,%1,%2,%3},{%4,%5,%6,%7},{%8,%9},{%0,%1,%2,%3};"
                 : "+f"(d[0]), "+f"(d[1]), "+f"(d[2]), "+f"(d[3])
                 : "r"(a[0]), "r"(a[1]), "r"(a[2]), "r"(a[3]), "r"(b0), "r"(b1));
}
__device__ __forceinline__ void cpasync16(uint32_t s, const void* g) {
    asm volatile("cp.async.cg.shared.global [%0],[%1],16;" :: "r"(s), "l"(g));
}
__device__ __forceinline__ float sqrt_approx(float x) {
    float y;
    asm("sqrt.approx.f32 %0, %1;" : "=f"(y) : "f"(x));
    return y;
}
__device__ __forceinline__ float sigm(float x) { return 1.0f / (1.0f + __expf(-x)); }

// ---------------- fused fp16 conversion (x + 4 weights, one launch) ----------
__device__ __forceinline__ ull pack_f16(float4 v) {
    const float* f = &v.x;
    ull p = 0;
#pragma unroll
    for (int j = 0; j < 4; j++)
        p |= (ull)__half_as_ushort(__float2half_rn(f[j])) << (16 * j);
    return p;
}
__global__ void conv_all(const float4* __restrict__ x,
                         const float4* __restrict__ w0, const float4* __restrict__ w1,
                         const float4* __restrict__ w2, const float4* __restrict__ w3,
                         ull* __restrict__ dx, ull* __restrict__ dw)
{
    const int gid = blockIdx.x * blockDim.x + threadIdx.x;
    const int NX = M_DIM * K_DIM / 4;          // 4194304
    if (gid < NX) {
        dx[gid] = pack_f16(x[gid]);
    } else {
        const int j = gid - NX;                // 0 .. 4*262144-1
        const int seg = j >> 18, off = j & 0x3FFFF;
        const float4* src = (seg == 0) ? w0 : (seg == 1) ? w1 : (seg == 2) ? w2 : w3;
        dw[j] = pack_f16(src[off]);
    }
}
// bias concat + decay coefficient (4096 threads)
__global__ void prep_kernel(const float* __restrict__ a, const float* __restrict__ b,
                            const float* __restrict__ c, const float* __restrict__ ldec,
                            float* __restrict__ dst, float* __restrict__ cd) {
    int t = blockIdx.x * blockDim.x + threadIdx.x;   // 4 x 1024
    if (t < 3072) {
        dst[t] = (t < 1024) ? a[t] : (t < 2048 ? b[t - 1024] : c[t - 2048]);
    } else {
        const int n = t - 3072;
        const float ld = ldec[n];
        const float sp = (ld > 20.0f) ? ld : log1pf(__expf(ld));
        cd[n] = -8.0f * sp;
    }
}

// ---------------- fp16 MMA GEMM ------------------------------------------------
constexpr int BM = 128, BN = 128, BK = 64, STAGES = 3;
constexpr int AB_BYTES = BM * BK * 2;          // 16384 per operand tile
constexpr int STAGE_BYTES = 2 * AB_BYTES;      // 32768 (A, B)
constexpr int GSMEM = STAGES * STAGE_BYTES;    // 98304 -> 2 CTAs/SM
constexpr int NT = K_DIM / BK;                 // 16

template<int OUT16>
__global__ void __launch_bounds__(256, 2)
gemm_f16(const __half* __restrict__ A, const __half* __restrict__ B,
         const float* __restrict__ bias, void* __restrict__ Cv, int ldc)
{
    extern __shared__ char smem[];
    const uint32_t sb = s2u(smem);
    const int tid = threadIdx.x, lane = tid & 31, wid = tid >> 5;
    const int wm = wid >> 2, wn = wid & 3;          // 2 x 4 warp grid
    const int mBase = blockIdx.y * BM, nBase = blockIdx.x * BN;

    const int lrow = tid >> 1;                 // 0..127
    const int lc0  = (tid & 1) * 4;            // 16B-chunk base: 0 or 4
    const char* gA = (const char*)(A + (size_t)(mBase + lrow) * K_DIM);
    const char* gB = (const char*)(B + (size_t)(nBase + lrow) * K_DIM);
    const uint32_t swBase = lrow * 128;

    auto issue = [&](int kt, int s) {
        const uint32_t st = sb + s * STAGE_BYTES;
#pragma unroll
        for (int m = 0; m < 2; m++) {
            const char* g = (m == 0 ? gA : gB) + kt * 128;
            const uint32_t t0 = st + m * AB_BYTES + swBase;
#pragma unroll
            for (int c = 0; c < 4; c++) {
                const int cc = lc0 + c;
                cpasync16(t0 + ((cc ^ (lrow & 7)) << 4), g + cc * 16);
            }
        }
        asm volatile("cp.async.commit_group;");
    };

    float acc[4][4][4];
#pragma unroll
    for (int a = 0; a < 4; a++)
#pragma unroll
        for (int b = 0; b < 4; b++)
#pragma unroll
            for (int c = 0; c < 4; c++) acc[a][b][c] = 0.0f;

    issue(0, 0);
    issue(1, 1);

    const int li = lane >> 3, lj = lane & 7;

    for (int kt = 0; kt < NT; kt++) {
        asm volatile("cp.async.wait_group %0;" :: "n"(1));
        __syncthreads();
        if (kt + 2 < NT) issue(kt + 2, (kt + 2) % STAGES);
        else asm volatile("cp.async.commit_group;");

        const uint32_t st = sb + (kt % STAGES) * STAGE_BYTES;
        const uint32_t aS = st, bS = st + AB_BYTES;

#pragma unroll
        for (int ks = 0; ks < BK / 16; ks++) {
            uint32_t ar[4][4], br[2][4];
#pragma unroll
            for (int mt = 0; mt < 4; mt++) {
                const int r  = wm * 64 + mt * 16 + ((li & 1) << 3) + lj;
                const int c8 = ks * 2 + (li >> 1);
                ldsm4(ar[mt], aS + r * 128 + ((c8 ^ (r & 7)) << 4));
            }
#pragma unroll
            for (int n2 = 0; n2 < 2; n2++) {
                const int r  = wn * 32 + n2 * 16 + ((li >> 1) << 3) + lj;
                const int c8 = ks * 2 + (li & 1);
                ldsm4(br[n2], bS + r * 128 + ((c8 ^ (r & 7)) << 4));
            }
#pragma unroll
            for (int mt = 0; mt < 4; mt++)
#pragma unroll
                for (int nt = 0; nt < 4; nt++) {
                    const int n2 = nt >> 1, hh = (nt & 1) * 2;
                    mma_f16(acc[mt][nt], ar[mt], br[n2][hh], br[n2][hh + 1]);
                }
        }
    }

    const int grp = lane >> 2, tq = lane & 3;
#pragma unroll
    for (int nt = 0; nt < 4; nt++) {
        const int col = nBase + wn * 32 + nt * 8 + tq * 2;
        const float2 bv = *(const float2*)&bias[col];
#pragma unroll
        for (int mt = 0; mt < 4; mt++) {
            const int r0 = mBase + wm * 64 + mt * 16 + grp;
            if (OUT16) {
                __half* C = (__half*)Cv;
                __half2 v0 = __floats2half2_rn(acc[mt][nt][0] + bv.x,
                                               acc[mt][nt][1] + bv.y);
                __half2 v1 = __floats2half2_rn(acc[mt][nt][2] + bv.x,
                                               acc[mt][nt][3] + bv.y);
                *(__half2*)&C[(size_t)r0 * ldc + col]       = v0;
                *(__half2*)&C[(size_t)(r0 + 8) * ldc + col] = v1;
            } else {
                float* C = (float*)Cv;
                float2 v0 = make_float2(acc[mt][nt][0] + bv.x, acc[mt][nt][1] + bv.y);
                float2 v1 = make_float2(acc[mt][nt][2] + bv.x, acc[mt][nt][3] + bv.y);
                *(float2*)&C[(size_t)r0 * ldc + col]       = v0;
                *(float2*)&C[(size_t)(r0 + 8) * ldc + col] = v1;
            }
        }
    }
}

// ---------------- Pass A: parallel gate computation ---------------------------
// One thread per 2 adjacent n. Computes a = sigm(c*sigm(r)),
// u = sqrt(1-a^2+eps)*sigm(i)*xp and stores packed (a,u) half2 pairs.
__global__ void gates_kernel()
{
    const int idx = blockIdx.x * 256 + threadIdx.x;   // 0 .. 8388607
    const int m  = idx >> 9;                          // row (b*S+s)
    const int nh = idx & 511;                         // half2 index (2 n's)
    const size_t base = (size_t)m * 3072 + nh * 2;

    const __half2 xv2 = *(const __half2*)&g_prj[base];
    const __half2 rv2 = *(const __half2*)&g_prj[base + 1024];
    const __half2 iv2 = *(const __half2*)&g_prj[base + 2048];
    const float2  c2  = *(const float2*)&g_c[nh * 2];

    const float rv0 = sigm(__low2float(rv2)),  rv1 = sigm(__high2float(rv2));
    const float iv0 = sigm(__low2float(iv2)),  iv1 = sigm(__high2float(iv2));
    const float a0  = sigm(c2.x * rv0),        a1  = sigm(c2.y * rv1);
    const float u0  = sqrt_approx(fmaf(-a0, a0, 1.000001f)) * iv0 * __low2float(xv2);
    const float u1  = sqrt_approx(fmaf(-a1, a1, 1.000001f)) * iv1 * __high2float(xv2);

    const __half2 p0 = __floats2half2_rn(a0, u0);
    const __half2 p1 = __floats2half2_rn(a1, u1);
    const uint32_t lo = *(const uint32_t*)&p0;
    const uint32_t hi = *(const uint32_t*)&p1;
    g_au[(size_t)m * 512 + nh] = (ull)lo | ((ull)hi << 32);
}

// ---------------- Pass B: light chunked scan ----------------------------------
// Inner step: 1x 4-byte load (independent of h) + 1 FMA. a < 0.5 strictly, so
// a 32-step warmup reconstructs state to < 2^-32: chunks fully independent.
constexpr int SC_CH = 32, SC_LEN = 128, SC_WARM = 32;

__global__ void scan_kernel(const float* __restrict__ h0,
                            __half* __restrict__ hs16,
                            float* __restrict__ hlast)
{
    const int n  = blockIdx.x * 128 + threadIdx.x;   // grid.x = 8
    const int b  = blockIdx.y;                       // 4
    const int ch = blockIdx.z;                       // 32
    const __half2* au2 = (const __half2*)g_au;
    const size_t baseA = ((size_t)b * S_DIM) * N_ST + n;   // au / hs rows

    float h; int s;
    if (ch == 0) { h = h0[b * N_ST + n]; s = 0; }
    else         { h = 0.0f; s = ch * SC_LEN - SC_WARM; }
    const int s1 = ch * SC_LEN, s2 = s1 + SC_LEN;

#pragma unroll 8
    for (; s < s1; ++s) {
        const __half2 v = au2[baseA + (size_t)s * N_ST];
        h = fmaf(__low2float(v), h, __high2float(v));
    }
#pragma unroll 8
    for (; s < s2; ++s) {
        const size_t idx = baseA + (size_t)s * N_ST;
        const __half2 v = au2[idx];
        h = fmaf(__low2float(v), h, __high2float(v));
        hs16[idx] = __float2half_rn(h);
    }
    if (ch == SC_CH - 1 && hlast) hlast[b * N_ST + n] = h;
}

// ---------------- host launcher -----------------------------------------------
extern "C" void kernel_launch(void* const* d_in, const int* in_sizes, int n_in,
                              void* d_out, int out_size)
{
    const float* x         = (const float*)d_in[0];
    const float* h0        = (const float*)d_in[1];
    const float* W_in      = (const float*)d_in[2];
    const float* b_in      = (const float*)d_in[3];
    const float* W_r       = (const float*)d_in[4];
    const float* b_r       = (const float*)d_in[5];
    const float* W_i       = (const float*)d_in[6];
    const float* b_i       = (const float*)d_in[7];
    const float* log_decay = (const float*)d_in[8];
    const float* W_out     = (const float*)d_in[9];
    const float* b_out     = (const float*)d_in[10];
    float* out = (float*)d_out;

    void *p_prj, *p_x16, *p_hs16, *p_w16, *p_b3, *p_c;
    cudaGetSymbolAddress(&p_prj,  g_prj);
    cudaGetSymbolAddress(&p_x16,  g_x16);
    cudaGetSymbolAddress(&p_hs16, g_hs16);
    cudaGetSymbolAddress(&p_w16,  g_w16);
    cudaGetSymbolAddress(&p_b3,   g_b3);
    cudaGetSymbolAddress(&p_c,    g_c);

    cudaFuncSetAttribute(gemm_f16<1>, cudaFuncAttributeMaxDynamicSharedMemorySize, GSMEM);
    cudaFuncSetAttribute(gemm_f16<0>, cudaFuncAttributeMaxDynamicSharedMemorySize, GSMEM);

    const size_t WSZ = 1024 * 1024;   // elements per weight matrix
    ull* w16 = (ull*)p_w16;

    // 1) single fused fp16 conversion (x + W_in + W_r + W_i + W_out)
    const int TOT4 = M_DIM * K_DIM / 4 + 4 * (int)(WSZ / 4);   // 5242880
    conv_all<<<TOT4 / 256, 256>>>(
        (const float4*)x, (const float4*)W_in, (const float4*)W_r,
        (const float4*)W_i, (const float4*)W_out, (ull*)p_x16, w16);
    prep_kernel<<<4, 1024>>>(b_in, b_r, b_i, log_decay,
                             (float*)p_b3, (float*)p_c);

    // 2) fused projections: [xp | r | i] = x @ [W_in;W_r;W_i]^T  (N = 3072, fp16 out)
    gemm_f16<1><<<dim3(24, 128), 256, GSMEM>>>(
        (const __half*)p_x16, (const __half*)p_w16,
        (const float*)p_b3, p_prj, 3072);

    // 3a) parallel gate pass: (a,u) for all 16.7M elements
    gates_kernel<<<(M_DIM * N_ST / 2) / 256, 256>>>();

    // 3b) light chunked scan
    const long long need = (long long)M_DIM * D_IN + (long long)B_DIM * N_ST;
    float* hlast = ((long long)out_size >= need) ? out + (size_t)M_DIM * D_IN : nullptr;
    scan_kernel<<<dim3(8, 4, SC_CH), 128>>>(h0, (__half*)p_hs16, hlast);

    // 4) output projection (N = 1024, fp32 out)
    gemm_f16<0><<<dim3(8, 128), 256, GSMEM>>>(
        (const __half*)p_hs16, (const __half*)(w16 + 3 * WSZ / 4),
        b_out, out, 1024);
}